// round 15
// baseline (speedup 1.0000x reference)
#include <cuda_runtime.h>
#include <math.h>
#include <float.h>

#define Bq 4
#define Sq 1024
#define Nk 16384
#define KK 16
#define G  16
#define NC (G * G * G)   // 4096 cells
#define BUFCAP 128

typedef unsigned long long ull;

// ---------------- scratch (device globals; no allocation allowed) ----------------
__device__ float g_cswq[128];
__device__ float g_cswk[128];
__device__ float g_csw2[128];
__device__ float g_consts[4];           // [0]=sum_bq, [1]=sum_bk, [2]=sum_b2
__device__ float g_qsum[Bq * Sq];
__device__ float g_ksum[Bq * Nk];
__device__ float g_attn[Bq * Sq * KK];
__device__ int   g_nidx[Bq * Sq * KK];
__device__ float g_acol[Bq * KK];
__device__ int    g_cellStart[Bq][NC + 1];
__device__ int    g_cellCur[Bq][NC];    // histogram, then running scatter offsets
__device__ float4 g_spos4[Bq * Nk];     // cell-sorted (x,y,z,kk)
__device__ int    g_sidx[Bq * Nk];      // original indices
__device__ int    g_qCur[Bq][NC];       // query histogram / running offsets
__device__ int    g_qord[Bq * Sq];      // cell-sorted query ids (per batch)

#define PERM(n) ((unsigned)((((n) & 511) << 5) | ((unsigned)(n) >> 9)))
#define FULLM 0xFFFFFFFFu

__device__ __forceinline__ int cell_of(float v) {
    int c = (int)(v * (float)G);
    return c < 0 ? 0 : (c > G - 1 ? G - 1 : c);
}

// ---------------- prep: column sums of Wq/Wk/W2, bias sums (384 threads) --------
__global__ void prep_kernel(const float* __restrict__ Wq, const float* __restrict__ bq,
                            const float* __restrict__ Wk, const float* __restrict__ bk,
                            const float* __restrict__ W2, const float* __restrict__ b2) {
    int t = threadIdx.x;          // 0..383
    int mtx = t >> 7;             // 0=Wq 1=Wk 2=W2
    int i = t & 127;
    const float* W = mtx == 0 ? Wq : (mtx == 1 ? Wk : W2);
    float sum = 0.f;
    for (int o = 0; o < 128; o++) sum += W[o * 128 + i];
    if (mtx == 0) g_cswq[i] = sum;
    else if (mtx == 1) g_cswk[i] = sum;
    else g_csw2[i] = sum;

    const float* bias = mtx == 0 ? bq : (mtx == 1 ? bk : b2);
    float v = bias[i];
    #pragma unroll
    for (int o = 16; o; o >>= 1) v += __shfl_xor_sync(FULLM, v, o);
    __shared__ float rb[12];
    if ((i & 31) == 0) rb[mtx * 4 + (i >> 5)] = v;
    __syncthreads();
    if (t < 3) g_consts[t == 0 ? 0 : (t == 1 ? 1 : 2)] =
        rb[t * 4] + rb[t * 4 + 1] + rb[t * 4 + 2] + rb[t * 4 + 3];
}

// ---------------- grid build ----------------
__global__ __launch_bounds__(256) void zero_kernel() {
    int i = blockIdx.x * 256 + threadIdx.x;       // 0 .. 2*Bq*NC-1
    if (i < Bq * NC) ((int*)g_cellCur)[i] = 0;
    else             ((int*)g_qCur)[i - Bq * NC] = 0;
}

// counts points (idx < Bq*Nk) and queries (rest) in one launch
__global__ __launch_bounds__(256) void count_all_kernel(const float* __restrict__ k_pos,
                                                        const float* __restrict__ q_pos) {
    int idx = blockIdx.x * 256 + threadIdx.x;     // 0 .. Bq*(Nk+Sq)-1
    if (idx < Bq * Nk) {
        int b = idx >> 14;
        const float* kp = k_pos + (size_t)idx * 3;
        int cx = cell_of(kp[0]), cy = cell_of(kp[1]), cz = cell_of(kp[2]);
        atomicAdd(&g_cellCur[b][(cz * G + cy) * G + cx], 1);
    } else {
        int qi = idx - Bq * Nk;
        int b = qi >> 10;
        const float* qp = q_pos + (size_t)qi * 3;
        int cx = cell_of(qp[0]), cy = cell_of(qp[1]), cz = cell_of(qp[2]);
        atomicAdd(&g_qCur[b][(cz * G + cy) * G + cx], 1);
    }
}

// blockIdx.x in [0, 2*Bq): first Bq -> point grid (also writes cellStart),
// last Bq -> query grid (running offsets only).
__global__ __launch_bounds__(1024) void scan_kernel() {
    int bb = blockIdx.x, t = threadIdx.x;
    int isQ = bb >= Bq;
    int b = isQ ? bb - Bq : bb;
    int* cur = isQ ? g_qCur[b] : g_cellCur[b];
    __shared__ int part[1024];
    int base = t * 4;
    int c0 = cur[base], c1 = cur[base + 1], c2 = cur[base + 2], c3 = cur[base + 3];
    int s = c0 + c1 + c2 + c3;
    part[t] = s;
    __syncthreads();
    for (int o = 1; o < 1024; o <<= 1) {
        int v = (t >= o) ? part[t - o] : 0;
        __syncthreads();
        part[t] += v;
        __syncthreads();
    }
    int run = part[t] - s;
    if (!isQ) {
        g_cellStart[b][base] = run;     cur[base] = run;     run += c0;
        g_cellStart[b][base + 1] = run; cur[base + 1] = run; run += c1;
        g_cellStart[b][base + 2] = run; cur[base + 2] = run; run += c2;
        g_cellStart[b][base + 3] = run; cur[base + 3] = run; run += c3;
        if (t == 1023) g_cellStart[b][NC] = run;
    } else {
        cur[base] = run;     run += c0;
        cur[base + 1] = run; run += c1;
        cur[base + 2] = run; run += c2;
        cur[base + 3] = run;
    }
}

__global__ __launch_bounds__(256) void scatter_all_kernel(const float* __restrict__ k_pos,
                                                          const float* __restrict__ q_pos) {
    int idx = blockIdx.x * 256 + threadIdx.x;     // 0 .. Bq*(Nk+Sq)-1
    if (idx < Bq * Nk) {
        int b = idx >> 14, n = idx & (Nk - 1);
        const float* kp = k_pos + (size_t)idx * 3;
        float x = kp[0], y = kp[1], z = kp[2];
        float kk = x * x + y * y + z * z;         // same expression as passing kernel
        int cx = cell_of(x), cy = cell_of(y), cz = cell_of(z);
        int pos = atomicAdd(&g_cellCur[b][(cz * G + cy) * G + cx], 1);
        g_spos4[(size_t)b * Nk + pos] = make_float4(x, y, z, kk);
        g_sidx[(size_t)b * Nk + pos] = n;
    } else {
        int qi = idx - Bq * Nk;
        int b = qi >> 10, s = qi & (Sq - 1);
        const float* qp = q_pos + (size_t)qi * 3;
        int cx = cell_of(qp[0]), cy = cell_of(qp[1]), cz = cell_of(qp[2]);
        int pos = atomicAdd(&g_qCur[b][(cz * G + cy) * G + cx], 1);
        g_qord[b * Sq + pos] = s;
    }
}

// ---------------- row sums: feat[row,:] . csw + bias_sum ----------------
__global__ __launch_bounds__(256) void rowsum_kernel(const float* __restrict__ feat,
                                                     int rows, int mode) {
    __shared__ float sc[128];
    int t = threadIdx.x;
    if (t < 128) sc[t] = mode ? g_cswq[t] : g_cswk[t];
    __syncthreads();
    int row = blockIdx.x * 8 + (t >> 5);
    if (row >= rows) return;
    int lane = t & 31;
    float4 v = ((const float4*)feat)[(size_t)row * 32 + lane];
    float4 c = ((const float4*)sc)[lane];
    float d = v.x * c.x + v.y * c.y + v.z * c.z + v.w * c.w;
    #pragma unroll
    for (int o = 16; o; o >>= 1) d += __shfl_xor_sync(FULLM, d, o);
    if (lane == 0) {
        float bs = mode ? g_consts[0] : g_consts[1];
        if (mode) g_qsum[row] = d + bs;
        else      g_ksum[row] = d + bs;
    }
}

// ---------------- grid KNN: ONE WARP per query, buffered candidate replay ------
// Lanes evaluate points in parallel; candidates passing the (possibly stale,
// hence conservative) threshold are compacted into a per-warp SMEM buffer via
// ballot+popc. The buffer is replayed by all 32 lanes (broadcast LDS) into an
// identical replicated top-16 before every ring-stop check and on near-overflow.
// Exact key compare at replay => selected top-16 identical to R11/R14.
__global__ __launch_bounds__(256) void knn_warp_kernel(const float* __restrict__ q_pos) {
    __shared__ __align__(16) ull sBuf[8][BUFCAP];      // 8 warps * 1KB

    int warpL = threadIdx.x >> 5;
    int lane  = threadIdx.x & 31;
    int warpId = blockIdx.x * 8 + warpL;               // 0 .. Bq*Sq-1 (sorted pos)
    int b = warpId >> 10;
    int s = g_qord[warpId];
    int gq = b * Sq + s;

    const float* qp = q_pos + (size_t)gq * 3;
    float qx = qp[0], qy = qp[1], qz = qp[2];
    float qq = qx * qx + qy * qy + qz * qz;            // same expression as passing kernel
    int cx = cell_of(qx), cy = cell_of(qy), cz = cell_of(qz);

    ull bK[KK];                                        // identical in all lanes
    #pragma unroll
    for (int j = 0; j < KK; j++) bK[j] = 0xFFFFFFFFFFFFFFFFull;
    unsigned thr = 0xFFFFFFFFu;                        // NaN bits until 16 filled
    int bufCnt = 0;
    ull* buf = sBuf[warpL];

    const float4* sp = g_spos4 + (size_t)b * Nk;
    const int*    si = g_sidx  + (size_t)b * Nk;
    const int*    cs = g_cellStart[b];
    const float h = 1.0f / (float)G;

#define FLUSHBUF()                                                          \
    {                                                                       \
        for (int i = 0; i < bufCnt; i++) {                                  \
            ull key = buf[i];                                               \
            if (key < bK[KK - 1]) {                                         \
                bK[KK - 1] = key;                                           \
                _Pragma("unroll")                                           \
                for (int jj = KK - 1; jj > 0; jj--) {                       \
                    if (bK[jj] < bK[jj - 1]) {                              \
                        ull tk = bK[jj]; bK[jj] = bK[jj - 1]; bK[jj - 1] = tk; \
                    } else break;                                           \
                }                                                           \
            }                                                               \
        }                                                                   \
        thr = (unsigned)(bK[KK - 1] >> 32);                                 \
        bufCnt = 0;                                                         \
    }

#define SEGMENT(J0, J1)                                                     \
    for (int base = (J0); base < (J1); base += 32) {                        \
        int j = base + lane;                                                \
        int act = j < (J1);                                                 \
        int jc = act ? j : (J1) - 1;                                        \
        float4 pt = sp[jc];                                                 \
        int n = si[jc];                                                     \
        float qk = fmaf(qz, pt.z, fmaf(qy, pt.y, qx * pt.x));               \
        float d2 = (qq - 2.f * qk) + pt.w;                                  \
        unsigned d2b = __float_as_uint(d2);                                 \
        int pass = act && d2b <= thr;                                       \
        unsigned m = __ballot_sync(FULLM, pass);                            \
        if (pass) {                                                         \
            int off = bufCnt + __popc(m & ((1u << lane) - 1u));             \
            buf[off] = ((ull)d2b << 32) | (ull)PERM(n);                     \
        }                                                                   \
        bufCnt += __popc(m);                                                \
        if (bufCnt > BUFCAP - 33) FLUSHBUF()                                \
    }

    for (int r = 0; r < G; r++) {
        if (r >= 1) {
            FLUSHBUF()
            float thrF = __uint_as_float(thr);        // NaN until 16 found
            int rIn = r - 1;
            float mg = 1e30f;
            if (cx - rIn > 0)     mg = fminf(mg, qx - (float)(cx - rIn) * h);
            if (cx + rIn < G - 1) mg = fminf(mg, (float)(cx + rIn + 1) * h - qx);
            if (cy - rIn > 0)     mg = fminf(mg, qy - (float)(cy - rIn) * h);
            if (cy + rIn < G - 1) mg = fminf(mg, (float)(cy + rIn + 1) * h - qy);
            if (cz - rIn > 0)     mg = fminf(mg, qz - (float)(cz - rIn) * h);
            if (cz + rIn < G - 1) mg = fminf(mg, (float)(cz + rIn + 1) * h - qz);
            if (mg > 0.f && (mg * mg - 1e-5f) > thrF) break;   // warp-uniform
        }
        int zlo = max(0, cz - r), zhi = min(G - 1, cz + r);
        for (int iz = zlo; iz <= zhi; iz++) {
            int adz = iz - cz; if (adz < 0) adz = -adz;
            int ylo = max(0, cy - r), yhi = min(G - 1, cy + r);
            for (int iy = ylo; iy <= yhi; iy++) {
                int ady = iy - cy; if (ady < 0) ady = -ady;
                int rowBase = (iz * G + iy) * G;
                if (adz == r || ady == r) {
                    int xlo = max(0, cx - r), xhi = min(G - 1, cx + r);
                    int j0 = cs[rowBase + xlo], j1 = cs[rowBase + xhi + 1];
                    SEGMENT(j0, j1)
                } else {
                    if (cx - r >= 0) {
                        int c = rowBase + cx - r;
                        int j0 = cs[c], j1 = cs[c + 1];
                        SEGMENT(j0, j1)
                    }
                    if (cx + r <= G - 1) {
                        int c = rowBase + cx + r;
                        int j0 = cs[c], j1 = cs[c + 1];
                        SEGMENT(j0, j1)
                    }
                }
            }
        }
    }
    FLUSHBUF()
#undef SEGMENT
#undef FLUSHBUF

    if (lane == 0) {
        #pragma unroll
        for (int r2 = 0; r2 < KK; r2++) {
            unsigned pm = (unsigned)(bK[r2] & 0x3FFFull);
            g_nidx[gq * KK + r2] = (int)(((pm & 31u) << 9) | (pm >> 5));
        }
    }
}

// ---------------- PE-sum + scores + softmax(over k): 16 threads/query ----------
__global__ __launch_bounds__(256) void pe_kernel(const float* __restrict__ q_pos,
                                                 const float* __restrict__ k_pos,
                                                 const float* __restrict__ W1,
                                                 const float* __restrict__ b1) {
    constexpr int QPB = 16;
    __shared__ float sW1[384], sb1[128], sc2[128];

    int t  = threadIdx.x;
    int q  = t >> 4;
    int tq = t & 15;
    int b  = blockIdx.y;
    int s  = blockIdx.x * QPB + q;

    for (int i = t; i < 384; i += 256) sW1[i] = W1[i];
    if (t < 128) { sb1[t] = b1[t]; sc2[t] = g_csw2[t]; }
    __syncthreads();

    int gi = (b * Sq + s) * KK + tq;
    int myn = g_nidx[gi];

    const float* qp = q_pos + ((size_t)(b * Sq + s)) * 3;
    float qx = qp[0], qy = qp[1], qz = qp[2];
    const float* kp = k_pos + ((size_t)b * Nk + myn) * 3;
    float rx = qx - kp[0], ry = qy - kp[1], rz = qz - kp[2];
    float acc = 0.f;
    #pragma unroll 8
    for (int i = 0; i < 128; i++) {
        float hh = fmaf(sW1[i * 3], rx, fmaf(sW1[i * 3 + 1], ry, fmaf(sW1[i * 3 + 2], rz, sb1[i])));
        hh = fmaxf(hh, 0.f);
        acc = fmaf(sc2[i], hh, acc);
    }
    float score = g_qsum[b * Sq + s] - g_ksum[b * Nk + myn] + acc + g_consts[2];

    float m = score;
    #pragma unroll
    for (int o = 8; o; o >>= 1) m = fmaxf(m, __shfl_xor_sync(FULLM, m, o, 16));
    float e = expf(score - m);
    float sum = e;
    #pragma unroll
    for (int o = 8; o; o >>= 1) sum += __shfl_xor_sync(FULLM, sum, o, 16);
    g_attn[gi] = e / sum;
}

// ---------------- column sums of attn over S, per (b, slot j) ----------------
__global__ __launch_bounds__(256) void colsum_kernel() {
    int b = blockIdx.x >> 4, j = blockIdx.x & 15;
    float s = 0.f;
    for (int ss = threadIdx.x; ss < Sq; ss += 256) s += g_attn[(b * Sq + ss) * KK + j];
    #pragma unroll
    for (int o = 16; o; o >>= 1) s += __shfl_xor_sync(FULLM, s, o);
    __shared__ float r[8];
    if ((threadIdx.x & 31) == 0) r[threadIdx.x >> 5] = s;
    __syncthreads();
    if (threadIdx.x == 0) {
        float tt = 0.f;
        #pragma unroll
        for (int w = 0; w < 8; w++) tt += r[w];
        g_acol[blockIdx.x] = tt;
    }
}

// ---------------- final: normalized gather-aggregate + single GEMM row ----------------
__global__ __launch_bounds__(128) void final_kernel(const float* __restrict__ k_feat,
                                                    const float* __restrict__ Wv,
                                                    const float* __restrict__ bv,
                                                    float* __restrict__ out) {
    constexpr int QPB2 = 32;
    extern __shared__ float sm[];
    float* WvS  = sm;                    // 128 rows x 132 stride (padded, conflict-free f4)
    float* sAgg = sm + 128 * 132;        // 128
    float* sA   = sAgg + 128;            // 16
    int*   sI   = (int*)(sA + 16);       // 16

    int t = threadIdx.x;
    for (int id = t; id < 128 * 128; id += 128) {
        int o = id >> 7, i = id & 127;
        WvS[o * 132 + i] = Wv[id];
    }
    float bvt = bv[t];

    for (int ql = 0; ql < QPB2; ql++) {
        int gq = blockIdx.x * QPB2 + ql;
        int b = gq >> 10;
        __syncthreads();
        if (t < 16) {
            float a = g_attn[gq * KK + t];
            a = a / (g_acol[b * KK + t] + 1e-6f);
            sA[t] = a;
            sI[t] = g_nidx[gq * KK + t];
        }
        __syncthreads();

        float agg = 0.f, asum = 0.f;
        #pragma unroll
        for (int j = 0; j < KK; j++) {
            float a = sA[j];
            asum += a;
            const float* vr = k_feat + ((size_t)(b * Nk) + sI[j]) * 128;
            agg = fmaf(a, vr[t], agg);
        }
        sAgg[t] = agg;
        __syncthreads();

        float a0 = 0.f, a1 = 0.f, a2 = 0.f, a3 = 0.f;
        const float4* wrow = (const float4*)(WvS + t * 132);
        const float4* aggv = (const float4*)sAgg;
        #pragma unroll
        for (int i4 = 0; i4 < 32; i4++) {
            float4 w = wrow[i4];
            float4 g = aggv[i4];
            a0 = fmaf(w.x, g.x, a0);
            a1 = fmaf(w.y, g.y, a1);
            a2 = fmaf(w.z, g.z, a2);
            a3 = fmaf(w.w, g.w, a3);
        }
        out[(size_t)gq * 128 + t] = ((a0 + a1) + (a2 + a3)) + asum * bvt;
    }
}

// ---------------- launch ----------------
extern "C" void kernel_launch(void* const* d_in, const int* in_sizes, int n_in,
                              void* d_out, int out_size) {
    const float* q_feat = (const float*)d_in[0];
    const float* k_feat = (const float*)d_in[1];
    const float* q_pos  = (const float*)d_in[2];
    const float* k_pos  = (const float*)d_in[3];
    const float* Wq     = (const float*)d_in[4];
    const float* bq     = (const float*)d_in[5];
    const float* Wk     = (const float*)d_in[6];
    const float* bk     = (const float*)d_in[7];
    const float* Wv     = (const float*)d_in[8];
    const float* bv     = (const float*)d_in[9];
    const float* W1     = (const float*)d_in[10];
    const float* b1     = (const float*)d_in[11];
    const float* W2     = (const float*)d_in[12];
    const float* b2     = (const float*)d_in[13];
    float* out = (float*)d_out;

    prep_kernel<<<1, 384>>>(Wq, bq, Wk, bk, W2, b2);
    zero_kernel<<<(2 * Bq * NC) / 256, 256>>>();
    count_all_kernel<<<(Bq * (Nk + Sq)) / 256, 256>>>(k_pos, q_pos);
    scan_kernel<<<2 * Bq, 1024>>>();
    scatter_all_kernel<<<(Bq * (Nk + Sq)) / 256, 256>>>(k_pos, q_pos);
    rowsum_kernel<<<(Bq * Nk) / 8, 256>>>(k_feat, Bq * Nk, 0);
    rowsum_kernel<<<(Bq * Sq) / 8, 256>>>(q_feat, Bq * Sq, 1);
    knn_warp_kernel<<<(Bq * Sq) / 8, 256>>>(q_pos);
    pe_kernel<<<dim3(Sq / 16, Bq), 256>>>(q_pos, k_pos, W1, b1);
    colsum_kernel<<<Bq * KK, 256>>>();

    int smemF = (128 * 132 + 128 + 16 + 16) * (int)sizeof(float);
    cudaFuncSetAttribute(final_kernel, cudaFuncAttributeMaxDynamicSharedMemorySize, smemF);
    final_kernel<<<(Bq * Sq) / 32, 128, smemF>>>(k_feat, Wv, bv, out);
}

// round 16
// speedup vs baseline: 2.6495x; 2.6495x over previous
#include <cuda_runtime.h>
#include <math.h>
#include <float.h>

#define Bq 4
#define Sq 1024
#define Nk 16384
#define KK 16
#define G  16
#define NC (G * G * G)   // 4096 cells

typedef unsigned long long ull;

// ---------------- scratch (device globals; no allocation allowed) ----------------
__device__ float g_cswq[128];
__device__ float g_cswk[128];
__device__ float g_csw2[128];
__device__ float g_consts[4];           // [0]=sum_bq, [1]=sum_bk, [2]=sum_b2
__device__ float g_qsum[Bq * Sq];
__device__ float g_ksum[Bq * Nk];
__device__ float g_attn[Bq * Sq * KK];
__device__ int   g_nidx[Bq * Sq * KK];
__device__ float g_acol[Bq * KK];
__device__ int    g_cellStart[Bq][NC + 1];
__device__ int    g_cellCur[Bq][NC];    // histogram, then running scatter offsets
__device__ float4 g_spos4[Bq * Nk];     // cell-sorted (x,y,z,kk)
__device__ int    g_sidx[Bq * Nk];      // original indices
__device__ int    g_qCur[Bq][NC];       // query histogram / running offsets
__device__ int    g_qord[Bq * Sq];      // cell-sorted query ids (per batch)

#define PERM(n) ((unsigned)((((n) & 511) << 5) | ((unsigned)(n) >> 9)))
#define FULLM 0xFFFFFFFFu

__device__ __forceinline__ int cell_of(float v) {
    int c = (int)(v * (float)G);
    return c < 0 ? 0 : (c > G - 1 ? G - 1 : c);
}

// ---------------- prep (block 128) + zero grids (blocks 0..127) ----------------
__global__ __launch_bounds__(384) void prep_zero_kernel(
        const float* __restrict__ Wq, const float* __restrict__ bq,
        const float* __restrict__ Wk, const float* __restrict__ bk,
        const float* __restrict__ W2, const float* __restrict__ b2) {
    int t = threadIdx.x;
    if (blockIdx.x < 128) {
        int i = blockIdx.x * 384 + t;               // 0 .. 49151 ; need 32768
        if (i < Bq * NC) ((int*)g_cellCur)[i] = 0;
        else if (i < 2 * Bq * NC) ((int*)g_qCur)[i - Bq * NC] = 0;
        return;
    }
    // prep: 384 threads
    int mtx = t >> 7;             // 0=Wq 1=Wk 2=W2
    int i = t & 127;
    const float* W = mtx == 0 ? Wq : (mtx == 1 ? Wk : W2);
    float sum = 0.f;
    for (int o = 0; o < 128; o++) sum += W[o * 128 + i];
    if (mtx == 0) g_cswq[i] = sum;
    else if (mtx == 1) g_cswk[i] = sum;
    else g_csw2[i] = sum;

    const float* bias = mtx == 0 ? bq : (mtx == 1 ? bk : b2);
    float v = bias[i];
    #pragma unroll
    for (int o = 16; o; o >>= 1) v += __shfl_xor_sync(FULLM, v, o);
    __shared__ float rb[12];
    if ((i & 31) == 0) rb[mtx * 4 + (i >> 5)] = v;
    __syncthreads();
    if (t < 3) g_consts[t] = rb[t * 4] + rb[t * 4 + 1] + rb[t * 4 + 2] + rb[t * 4 + 3];
}

// ---------------- counts: points and queries in one launch ----------------
__global__ __launch_bounds__(256) void count_all_kernel(const float* __restrict__ k_pos,
                                                        const float* __restrict__ q_pos) {
    int idx = blockIdx.x * 256 + threadIdx.x;     // 0 .. Bq*(Nk+Sq)-1
    if (idx < Bq * Nk) {
        int b = idx >> 14;
        const float* kp = k_pos + (size_t)idx * 3;
        int cx = cell_of(kp[0]), cy = cell_of(kp[1]), cz = cell_of(kp[2]);
        atomicAdd(&g_cellCur[b][(cz * G + cy) * G + cx], 1);
    } else {
        int qi = idx - Bq * Nk;
        int b = qi >> 10;
        const float* qp = q_pos + (size_t)qi * 3;
        int cx = cell_of(qp[0]), cy = cell_of(qp[1]), cz = cell_of(qp[2]);
        atomicAdd(&g_qCur[b][(cz * G + cy) * G + cx], 1);
    }
}

// ---------------- scan: warp-shuffle based (blocks: 0..Bq-1 pts, Bq..2Bq-1 qs) --
__global__ __launch_bounds__(1024) void scan_kernel() {
    int bb = blockIdx.x, t = threadIdx.x;
    int isQ = bb >= Bq;
    int b = isQ ? bb - Bq : bb;
    int* cur = isQ ? g_qCur[b] : g_cellCur[b];
    int lane = t & 31, wid = t >> 5;
    __shared__ int warpTot[32];

    int base = t * 4;
    int c0 = cur[base], c1 = cur[base + 1], c2 = cur[base + 2], c3 = cur[base + 3];
    int s = c0 + c1 + c2 + c3;
    // inclusive warp scan of s
    int sc = s;
    #pragma unroll
    for (int o = 1; o < 32; o <<= 1) {
        int v = __shfl_up_sync(FULLM, sc, o);
        if (lane >= o) sc += v;
    }
    if (lane == 31) warpTot[wid] = sc;
    __syncthreads();
    if (wid == 0) {
        int w = warpTot[lane];
        #pragma unroll
        for (int o = 1; o < 32; o <<= 1) {
            int v = __shfl_up_sync(FULLM, w, o);
            if (lane >= o) w += v;
        }
        warpTot[lane] = w;
    }
    __syncthreads();
    int run = sc - s + (wid ? warpTot[wid - 1] : 0);   // exclusive prefix
    if (!isQ) {
        g_cellStart[b][base] = run;     cur[base] = run;     run += c0;
        g_cellStart[b][base + 1] = run; cur[base + 1] = run; run += c1;
        g_cellStart[b][base + 2] = run; cur[base + 2] = run; run += c2;
        g_cellStart[b][base + 3] = run; cur[base + 3] = run; run += c3;
        if (t == 1023) g_cellStart[b][NC] = run;
    } else {
        cur[base] = run;     run += c0;
        cur[base + 1] = run; run += c1;
        cur[base + 2] = run; run += c2;
        cur[base + 3] = run;
    }
}

__global__ __launch_bounds__(256) void scatter_all_kernel(const float* __restrict__ k_pos,
                                                          const float* __restrict__ q_pos) {
    int idx = blockIdx.x * 256 + threadIdx.x;     // 0 .. Bq*(Nk+Sq)-1
    if (idx < Bq * Nk) {
        int b = idx >> 14, n = idx & (Nk - 1);
        const float* kp = k_pos + (size_t)idx * 3;
        float x = kp[0], y = kp[1], z = kp[2];
        float kk = x * x + y * y + z * z;         // same expression as passing kernel
        int cx = cell_of(x), cy = cell_of(y), cz = cell_of(z);
        int pos = atomicAdd(&g_cellCur[b][(cz * G + cy) * G + cx], 1);
        g_spos4[(size_t)b * Nk + pos] = make_float4(x, y, z, kk);
        g_sidx[(size_t)b * Nk + pos] = n;
    } else {
        int qi = idx - Bq * Nk;
        int b = qi >> 10, s = qi & (Sq - 1);
        const float* qp = q_pos + (size_t)qi * 3;
        int cx = cell_of(qp[0]), cy = cell_of(qp[1]), cz = cell_of(qp[2]);
        int pos = atomicAdd(&g_qCur[b][(cz * G + cy) * G + cx], 1);
        g_qord[b * Sq + pos] = s;
    }
}

// ---------------- row sums for BOTH k_feat and q_feat in one launch ------------
__global__ __launch_bounds__(256) void rowsum_all_kernel(const float* __restrict__ k_feat,
                                                         const float* __restrict__ q_feat) {
    __shared__ float sck[128], scq[128];
    int t = threadIdx.x;
    if (t < 128) { sck[t] = g_cswk[t]; scq[t] = g_cswq[t]; }
    __syncthreads();
    int gr = blockIdx.x * 8 + (t >> 5);           // global row 0 .. Bq*(Nk+Sq)-1
    int lane = t & 31;
    int isQ = gr >= Bq * Nk;
    int row = isQ ? gr - Bq * Nk : gr;
    const float* feat = isQ ? q_feat : k_feat;
    const float* sc = isQ ? scq : sck;
    float4 v = ((const float4*)feat)[(size_t)row * 32 + lane];
    float4 c = ((const float4*)sc)[lane];
    float d = v.x * c.x + v.y * c.y + v.z * c.z + v.w * c.w;
    #pragma unroll
    for (int o = 16; o; o >>= 1) d += __shfl_xor_sync(FULLM, d, o);
    if (lane == 0) {
        if (isQ) g_qsum[row] = d + g_consts[0];
        else     g_ksum[row] = d + g_consts[1];
    }
}

// ---------------- grid KNN: ONE WARP per query (R14 skeleton) ----------
// + geometric pruning of planes/rows/cells using the same 1e-5 slack and
//   NaN-before-fill semantics as the validated ring-stop test.
// + passing lanes pre-build the 64-bit key; one 64-bit shfl per candidate.
// Selection semantics identical to R11/R14 (same superset, same exact keys).
__global__ __launch_bounds__(256) void knn_warp_kernel(const float* __restrict__ q_pos) {
    int warpId = (blockIdx.x * 256 + threadIdx.x) >> 5;   // 0 .. Bq*Sq-1 (sorted pos)
    int lane = threadIdx.x & 31;
    int b = warpId >> 10;
    int s = g_qord[warpId];
    int gq = b * Sq + s;

    const float* qp = q_pos + (size_t)gq * 3;
    float qx = qp[0], qy = qp[1], qz = qp[2];
    float qq = qx * qx + qy * qy + qz * qz;       // same expression as passing kernel
    int cx = cell_of(qx), cy = cell_of(qy), cz = cell_of(qz);

    ull bK[KK];                                    // identical in all lanes
    #pragma unroll
    for (int j = 0; j < KK; j++) bK[j] = 0xFFFFFFFFFFFFFFFFull;
    unsigned thr = 0xFFFFFFFFu;                    // NaN bits until 16 filled

    const float4* sp = g_spos4 + (size_t)b * Nk;
    const int*    si = g_sidx  + (size_t)b * Nk;
    const int*    cs = g_cellStart[b];
    const float h = 1.0f / (float)G;

    // distance from q to a 1D cell slab [c*h, (c+1)*h]
#define SLABD(qc, c) fmaxf(0.f, fmaxf((float)(c) * h - (qc), (qc) - (float)((c) + 1) * h))

#define SEGMENT(J0, J1)                                                     \
    for (int base = (J0); base < (J1); base += 32) {                        \
        int j = base + lane;                                                \
        int act = j < (J1);                                                 \
        int jc = act ? j : (J1) - 1;                                        \
        float4 pt = sp[jc];                                                 \
        float qk = fmaf(qz, pt.z, fmaf(qy, pt.y, qx * pt.x));               \
        float d2 = (qq - 2.f * qk) + pt.w;                                  \
        unsigned d2b = __float_as_uint(d2);                                 \
        int pass = act && d2b <= thr;                                       \
        ull key = 0;                                                        \
        if (pass) key = ((ull)d2b << 32) | (ull)PERM(si[jc]);               \
        unsigned m = __ballot_sync(FULLM, pass);                            \
        while (m) {                                                         \
            int src = __ffs(m) - 1; m &= m - 1;                             \
            unsigned klo = __shfl_sync(FULLM, (unsigned)key, src);          \
            unsigned khi = __shfl_sync(FULLM, (unsigned)(key >> 32), src);  \
            ull ck = ((ull)khi << 32) | (ull)klo;                           \
            if (ck < bK[KK - 1]) {                                          \
                bK[KK - 1] = ck;                                            \
                _Pragma("unroll")                                           \
                for (int jj = KK - 1; jj > 0; jj--) {                       \
                    if (bK[jj] < bK[jj - 1]) {                              \
                        ull tk = bK[jj]; bK[jj] = bK[jj - 1]; bK[jj - 1] = tk; \
                    } else break;                                           \
                }                                                           \
                thr = (unsigned)(bK[KK - 1] >> 32);                         \
            }                                                               \
        }                                                                   \
    }

    for (int r = 0; r < G; r++) {
        float thrF = __uint_as_float(thr);        // NaN until 16 found
        if (r >= 1) {
            int rIn = r - 1;
            float mg = 1e30f;
            if (cx - rIn > 0)     mg = fminf(mg, qx - (float)(cx - rIn) * h);
            if (cx + rIn < G - 1) mg = fminf(mg, (float)(cx + rIn + 1) * h - qx);
            if (cy - rIn > 0)     mg = fminf(mg, qy - (float)(cy - rIn) * h);
            if (cy + rIn < G - 1) mg = fminf(mg, (float)(cy + rIn + 1) * h - qy);
            if (cz - rIn > 0)     mg = fminf(mg, qz - (float)(cz - rIn) * h);
            if (cz + rIn < G - 1) mg = fminf(mg, (float)(cz + rIn + 1) * h - qz);
            if (mg > 0.f && (mg * mg - 1e-5f) > thrF) break;   // warp-uniform
        }
        int zlo = max(0, cz - r), zhi = min(G - 1, cz + r);
        for (int iz = zlo; iz <= zhi; iz++) {
            int adz = iz - cz; if (adz < 0) adz = -adz;
            float dz = SLABD(qz, iz);
            float dz2 = dz * dz;
            if (dz2 - 1e-5f > thrF) continue;                  // plane prune (NaN-safe)
            int ylo = max(0, cy - r), yhi = min(G - 1, cy + r);
            for (int iy = ylo; iy <= yhi; iy++) {
                int ady = iy - cy; if (ady < 0) ady = -ady;
                float dy = SLABD(qy, iy);
                float rowMin = dz2 + dy * dy;
                if (rowMin - 1e-5f > thrF) continue;           // row prune (NaN-safe)
                int rowBase = (iz * G + iy) * G;
                if (adz == r || ady == r) {
                    int xlo = max(0, cx - r), xhi = min(G - 1, cx + r);
                    int j0 = cs[rowBase + xlo], j1 = cs[rowBase + xhi + 1];
                    SEGMENT(j0, j1)
                } else {
                    if (cx - r >= 0) {
                        float dx = SLABD(qx, cx - r);
                        if (!(rowMin + dx * dx - 1e-5f > thrF)) {   // cell prune
                            int c = rowBase + cx - r;
                            int j0 = cs[c], j1 = cs[c + 1];
                            SEGMENT(j0, j1)
                        }
                    }
                    if (cx + r <= G - 1) {
                        float dx = SLABD(qx, cx + r);
                        if (!(rowMin + dx * dx - 1e-5f > thrF)) {   // cell prune
                            int c = rowBase + cx + r;
                            int j0 = cs[c], j1 = cs[c + 1];
                            SEGMENT(j0, j1)
                        }
                    }
                }
            }
        }
    }
#undef SEGMENT
#undef SLABD

    if (lane == 0) {
        #pragma unroll
        for (int r2 = 0; r2 < KK; r2++) {
            unsigned pm = (unsigned)(bK[r2] & 0x3FFFull);
            g_nidx[gq * KK + r2] = (int)(((pm & 31u) << 9) | (pm >> 5));
        }
    }
}

// ---------------- PE-sum + scores + softmax(over k): 16 threads/query ----------
__global__ __launch_bounds__(256) void pe_kernel(const float* __restrict__ q_pos,
                                                 const float* __restrict__ k_pos,
                                                 const float* __restrict__ W1,
                                                 const float* __restrict__ b1) {
    constexpr int QPB = 16;
    __shared__ float sW1[384], sb1[128], sc2[128];

    int t  = threadIdx.x;
    int q  = t >> 4;
    int tq = t & 15;
    int b  = blockIdx.y;
    int s  = blockIdx.x * QPB + q;

    for (int i = t; i < 384; i += 256) sW1[i] = W1[i];
    if (t < 128) { sb1[t] = b1[t]; sc2[t] = g_csw2[t]; }
    __syncthreads();

    int gi = (b * Sq + s) * KK + tq;
    int myn = g_nidx[gi];

    const float* qp = q_pos + ((size_t)(b * Sq + s)) * 3;
    float qx = qp[0], qy = qp[1], qz = qp[2];
    const float* kp = k_pos + ((size_t)b * Nk + myn) * 3;
    float rx = qx - kp[0], ry = qy - kp[1], rz = qz - kp[2];
    float acc = 0.f;
    #pragma unroll 8
    for (int i = 0; i < 128; i++) {
        float hh = fmaf(sW1[i * 3], rx, fmaf(sW1[i * 3 + 1], ry, fmaf(sW1[i * 3 + 2], rz, sb1[i])));
        hh = fmaxf(hh, 0.f);
        acc = fmaf(sc2[i], hh, acc);
    }
    float score = g_qsum[b * Sq + s] - g_ksum[b * Nk + myn] + acc + g_consts[2];

    float m = score;
    #pragma unroll
    for (int o = 8; o; o >>= 1) m = fmaxf(m, __shfl_xor_sync(FULLM, m, o, 16));
    float e = expf(score - m);
    float sum = e;
    #pragma unroll
    for (int o = 8; o; o >>= 1) sum += __shfl_xor_sync(FULLM, sum, o, 16);
    g_attn[gi] = e / sum;
}

// ---------------- column sums of attn over S, per (b, slot j) ----------------
__global__ __launch_bounds__(256) void colsum_kernel() {
    int b = blockIdx.x >> 4, j = blockIdx.x & 15;
    float s = 0.f;
    for (int ss = threadIdx.x; ss < Sq; ss += 256) s += g_attn[(b * Sq + ss) * KK + j];
    #pragma unroll
    for (int o = 16; o; o >>= 1) s += __shfl_xor_sync(FULLM, s, o);
    __shared__ float r[8];
    if ((threadIdx.x & 31) == 0) r[threadIdx.x >> 5] = s;
    __syncthreads();
    if (threadIdx.x == 0) {
        float tt = 0.f;
        #pragma unroll
        for (int w = 0; w < 8; w++) tt += r[w];
        g_acol[blockIdx.x] = tt;
    }
}

// ---------------- final: normalized gather-aggregate + single GEMM row ----------------
__global__ __launch_bounds__(128) void final_kernel(const float* __restrict__ k_feat,
                                                    const float* __restrict__ Wv,
                                                    const float* __restrict__ bv,
                                                    float* __restrict__ out) {
    constexpr int QPB2 = 8;
    extern __shared__ float sm[];
    float* WvS  = sm;                    // 128 rows x 132 stride (padded, conflict-free f4)
    float* sAgg = sm + 128 * 132;        // 128
    float* sA   = sAgg + 128;            // 16
    int*   sI   = (int*)(sA + 16);       // 16

    int t = threadIdx.x;
    // float4 staging of Wv
    for (int id = t; id < 128 * 32; id += 128) {
        int o = id >> 5, i4 = id & 31;
        float4 w = ((const float4*)Wv)[id];
        ((float4*)(WvS + o * 132))[i4] = w;
    }
    float bvt = bv[t];

    for (int ql = 0; ql < QPB2; ql++) {
        int gq = blockIdx.x * QPB2 + ql;
        int b = gq >> 10;
        __syncthreads();
        if (t < 16) {
            float a = g_attn[gq * KK + t];
            a = a / (g_acol[b * KK + t] + 1e-6f);
            sA[t] = a;
            sI[t] = g_nidx[gq * KK + t];
        }
        __syncthreads();

        float agg = 0.f, asum = 0.f;
        #pragma unroll
        for (int j = 0; j < KK; j++) {
            float a = sA[j];
            asum += a;
            const float* vr = k_feat + ((size_t)(b * Nk) + sI[j]) * 128;
            agg = fmaf(a, vr[t], agg);
        }
        sAgg[t] = agg;
        __syncthreads();

        float a0 = 0.f, a1 = 0.f, a2 = 0.f, a3 = 0.f;
        const float4* wrow = (const float4*)(WvS + t * 132);
        const float4* aggv = (const float4*)sAgg;
        #pragma unroll
        for (int i4 = 0; i4 < 32; i4++) {
            float4 w = wrow[i4];
            float4 g = aggv[i4];
            a0 = fmaf(w.x, g.x, a0);
            a1 = fmaf(w.y, g.y, a1);
            a2 = fmaf(w.z, g.z, a2);
            a3 = fmaf(w.w, g.w, a3);
        }
        out[(size_t)gq * 128 + t] = ((a0 + a1) + (a2 + a3)) + asum * bvt;
    }
}

// ---------------- launch ----------------
extern "C" void kernel_launch(void* const* d_in, const int* in_sizes, int n_in,
                              void* d_out, int out_size) {
    const float* q_feat = (const float*)d_in[0];
    const float* k_feat = (const float*)d_in[1];
    const float* q_pos  = (const float*)d_in[2];
    const float* k_pos  = (const float*)d_in[3];
    const float* Wq     = (const float*)d_in[4];
    const float* bq     = (const float*)d_in[5];
    const float* Wk     = (const float*)d_in[6];
    const float* bk     = (const float*)d_in[7];
    const float* Wv     = (const float*)d_in[8];
    const float* bv     = (const float*)d_in[9];
    const float* W1     = (const float*)d_in[10];
    const float* b1     = (const float*)d_in[11];
    const float* W2     = (const float*)d_in[12];
    const float* b2     = (const float*)d_in[13];
    float* out = (float*)d_out;

    prep_zero_kernel<<<129, 384>>>(Wq, bq, Wk, bk, W2, b2);
    count_all_kernel<<<(Bq * (Nk + Sq)) / 256, 256>>>(k_pos, q_pos);
    scan_kernel<<<2 * Bq, 1024>>>();
    scatter_all_kernel<<<(Bq * (Nk + Sq)) / 256, 256>>>(k_pos, q_pos);
    rowsum_all_kernel<<<(Bq * (Nk + Sq)) / 8, 256>>>(k_feat, q_feat);
    knn_warp_kernel<<<(Bq * Sq * 32) / 256, 256>>>(q_pos);
    pe_kernel<<<dim3(Sq / 16, Bq), 256>>>(q_pos, k_pos, W1, b1);
    colsum_kernel<<<Bq * KK, 256>>>();

    int smemF = (128 * 132 + 128 + 16 + 16) * (int)sizeof(float);
    cudaFuncSetAttribute(final_kernel, cudaFuncAttributeMaxDynamicSharedMemorySize, smemF);
    final_kernel<<<(Bq * Sq) / 8, 128, smemF>>>(k_feat, Wv, bv, out);
}

// round 17
// speedup vs baseline: 2.6787x; 1.0110x over previous
#include <cuda_runtime.h>
#include <math.h>
#include <float.h>

#define Bq 4
#define Sq 1024
#define Nk 16384
#define KK 16
#define G  16
#define NC (G * G * G)   // 4096 cells

typedef unsigned long long ull;

// ---------------- scratch (device globals; no allocation allowed) ----------------
__device__ float g_cswq[128];
__device__ float g_cswk[128];
__device__ float g_csw2[128];
__device__ float g_consts[4];           // [0]=sum_bq, [1]=sum_bk, [2]=sum_b2
__device__ float g_qsum[Bq * Sq];
__device__ float g_ksum[Bq * Nk];
__device__ float g_attn[Bq * Sq * KK];
__device__ int   g_nidx[Bq * Sq * KK];
__device__ float g_acol[Bq * KK];
__device__ int    g_cellStart[Bq][NC + 1];
__device__ int    g_cellCur[Bq][NC];    // histogram, then running scatter offsets
__device__ float4 g_spos4[Bq * Nk];     // cell-sorted (x,y,z,kk)
__device__ int    g_sidx[Bq * Nk];      // original indices
__device__ int    g_qCur[Bq][NC];       // query histogram / running offsets
__device__ int    g_qord[Bq * Sq];      // cell-sorted query ids (per batch)

#define PERM(n) ((unsigned)((((n) & 511) << 5) | ((unsigned)(n) >> 9)))
#define FULLM 0xFFFFFFFFu

__device__ __forceinline__ int cell_of(float v) {
    int c = (int)(v * (float)G);
    return c < 0 ? 0 : (c > G - 1 ? G - 1 : c);
}

// ---------------- prep (block 128) + zero grids (blocks 0..127) ----------------
__global__ __launch_bounds__(384) void prep_zero_kernel(
        const float* __restrict__ Wq, const float* __restrict__ bq,
        const float* __restrict__ Wk, const float* __restrict__ bk,
        const float* __restrict__ W2, const float* __restrict__ b2) {
    int t = threadIdx.x;
    if (blockIdx.x < 128) {
        int i = blockIdx.x * 384 + t;               // 0 .. 49151 ; need 32768
        if (i < Bq * NC) ((int*)g_cellCur)[i] = 0;
        else if (i < 2 * Bq * NC) ((int*)g_qCur)[i - Bq * NC] = 0;
        return;
    }
    // prep: 384 threads
    int mtx = t >> 7;             // 0=Wq 1=Wk 2=W2
    int i = t & 127;
    const float* W = mtx == 0 ? Wq : (mtx == 1 ? Wk : W2);
    float sum = 0.f;
    for (int o = 0; o < 128; o++) sum += W[o * 128 + i];
    if (mtx == 0) g_cswq[i] = sum;
    else if (mtx == 1) g_cswk[i] = sum;
    else g_csw2[i] = sum;

    const float* bias = mtx == 0 ? bq : (mtx == 1 ? bk : b2);
    float v = bias[i];
    #pragma unroll
    for (int o = 16; o; o >>= 1) v += __shfl_xor_sync(FULLM, v, o);
    __shared__ float rb[12];
    if ((i & 31) == 0) rb[mtx * 4 + (i >> 5)] = v;
    __syncthreads();
    if (t < 3) g_consts[t] = rb[t * 4] + rb[t * 4 + 1] + rb[t * 4 + 2] + rb[t * 4 + 3];
}

// ---------------- fused: rowsums (first CTAs) + cell counts (last CTAs) --------
#define RS_CTAS ((Bq * (Nk + Sq)) / 8)     // 8704
#define CNT_CTAS ((Bq * (Nk + Sq)) / 256)  // 272
__global__ __launch_bounds__(256) void count_rowsum_kernel(
        const float* __restrict__ k_pos, const float* __restrict__ q_pos,
        const float* __restrict__ k_feat, const float* __restrict__ q_feat) {
    int t = threadIdx.x;
    if (blockIdx.x < RS_CTAS) {
        // rowsum part
        __shared__ float sck[128], scq[128];
        if (t < 128) { sck[t] = g_cswk[t]; scq[t] = g_cswq[t]; }
        __syncthreads();
        int gr = blockIdx.x * 8 + (t >> 5);       // global row 0 .. Bq*(Nk+Sq)-1
        int lane = t & 31;
        int isQ = gr >= Bq * Nk;
        int row = isQ ? gr - Bq * Nk : gr;
        const float* feat = isQ ? q_feat : k_feat;
        const float* sc = isQ ? scq : sck;
        float4 v = ((const float4*)feat)[(size_t)row * 32 + lane];
        float4 c = ((const float4*)sc)[lane];
        float d = v.x * c.x + v.y * c.y + v.z * c.z + v.w * c.w;
        #pragma unroll
        for (int o = 16; o; o >>= 1) d += __shfl_xor_sync(FULLM, d, o);
        if (lane == 0) {
            if (isQ) g_qsum[row] = d + g_consts[0];
            else     g_ksum[row] = d + g_consts[1];
        }
        return;
    }
    // count part
    int idx = (blockIdx.x - RS_CTAS) * 256 + t;   // 0 .. Bq*(Nk+Sq)-1
    if (idx < Bq * Nk) {
        int b = idx >> 14;
        const float* kp = k_pos + (size_t)idx * 3;
        int cx = cell_of(kp[0]), cy = cell_of(kp[1]), cz = cell_of(kp[2]);
        atomicAdd(&g_cellCur[b][(cz * G + cy) * G + cx], 1);
    } else {
        int qi = idx - Bq * Nk;
        int b = qi >> 10;
        const float* qp = q_pos + (size_t)qi * 3;
        int cx = cell_of(qp[0]), cy = cell_of(qp[1]), cz = cell_of(qp[2]);
        atomicAdd(&g_qCur[b][(cz * G + cy) * G + cx], 1);
    }
}

// ---------------- scan: warp-shuffle based (blocks: 0..Bq-1 pts, Bq..2Bq-1 qs) --
__global__ __launch_bounds__(1024) void scan_kernel() {
    int bb = blockIdx.x, t = threadIdx.x;
    int isQ = bb >= Bq;
    int b = isQ ? bb - Bq : bb;
    int* cur = isQ ? g_qCur[b] : g_cellCur[b];
    int lane = t & 31, wid = t >> 5;
    __shared__ int warpTot[32];

    int base = t * 4;
    int c0 = cur[base], c1 = cur[base + 1], c2 = cur[base + 2], c3 = cur[base + 3];
    int s = c0 + c1 + c2 + c3;
    int sc = s;
    #pragma unroll
    for (int o = 1; o < 32; o <<= 1) {
        int v = __shfl_up_sync(FULLM, sc, o);
        if (lane >= o) sc += v;
    }
    if (lane == 31) warpTot[wid] = sc;
    __syncthreads();
    if (wid == 0) {
        int w = warpTot[lane];
        #pragma unroll
        for (int o = 1; o < 32; o <<= 1) {
            int v = __shfl_up_sync(FULLM, w, o);
            if (lane >= o) w += v;
        }
        warpTot[lane] = w;
    }
    __syncthreads();
    int run = sc - s + (wid ? warpTot[wid - 1] : 0);   // exclusive prefix
    if (!isQ) {
        g_cellStart[b][base] = run;     cur[base] = run;     run += c0;
        g_cellStart[b][base + 1] = run; cur[base + 1] = run; run += c1;
        g_cellStart[b][base + 2] = run; cur[base + 2] = run; run += c2;
        g_cellStart[b][base + 3] = run; cur[base + 3] = run; run += c3;
        if (t == 1023) g_cellStart[b][NC] = run;
    } else {
        cur[base] = run;     run += c0;
        cur[base + 1] = run; run += c1;
        cur[base + 2] = run; run += c2;
        cur[base + 3] = run;
    }
}

__global__ __launch_bounds__(256) void scatter_all_kernel(const float* __restrict__ k_pos,
                                                          const float* __restrict__ q_pos) {
    int idx = blockIdx.x * 256 + threadIdx.x;     // 0 .. Bq*(Nk+Sq)-1
    if (idx < Bq * Nk) {
        int b = idx >> 14, n = idx & (Nk - 1);
        const float* kp = k_pos + (size_t)idx * 3;
        float x = kp[0], y = kp[1], z = kp[2];
        float kk = x * x + y * y + z * z;         // same expression as passing kernel
        int cx = cell_of(x), cy = cell_of(y), cz = cell_of(z);
        int pos = atomicAdd(&g_cellCur[b][(cz * G + cy) * G + cx], 1);
        g_spos4[(size_t)b * Nk + pos] = make_float4(x, y, z, kk);
        g_sidx[(size_t)b * Nk + pos] = n;
    } else {
        int qi = idx - Bq * Nk;
        int b = qi >> 10, s = qi & (Sq - 1);
        const float* qp = q_pos + (size_t)qi * 3;
        int cx = cell_of(qp[0]), cy = cell_of(qp[1]), cz = cell_of(qp[2]);
        int pos = atomicAdd(&g_qCur[b][(cz * G + cy) * G + cx], 1);
        g_qord[b * Sq + pos] = s;
    }
}

// ---------------- grid KNN + PE + softmax: ONE WARP per query -------------------
// KNN part identical semantics to R16 (same d2 chain, key order, pruning).
// Tail: 2 lanes per neighbor compute PE-sum (64 hidden units each, pair-reduce),
// softmax across the 16 pair-scores via xor{2,4,8,16}; even lanes store attn/nidx.
__global__ __launch_bounds__(256) void knn_warp_kernel(const float* __restrict__ q_pos,
                                                       const float* __restrict__ k_pos,
                                                       const float* __restrict__ W1,
                                                       const float* __restrict__ b1) {
    __shared__ float sW1[384], sb1[128], sc2[128];
    {
        int t = threadIdx.x;
        for (int i = t; i < 384; i += 256) sW1[i] = W1[i];
        if (t < 128) { sb1[t] = b1[t]; sc2[t] = g_csw2[t]; }
        __syncthreads();
    }

    int warpId = (blockIdx.x * 256 + threadIdx.x) >> 5;   // 0 .. Bq*Sq-1 (sorted pos)
    int lane = threadIdx.x & 31;
    int b = warpId >> 10;
    int s = g_qord[warpId];
    int gq = b * Sq + s;

    const float* qp = q_pos + (size_t)gq * 3;
    float qx = qp[0], qy = qp[1], qz = qp[2];
    float qq = qx * qx + qy * qy + qz * qz;       // same expression as passing kernel
    int cx = cell_of(qx), cy = cell_of(qy), cz = cell_of(qz);

    ull bK[KK];                                    // identical in all lanes
    #pragma unroll
    for (int j = 0; j < KK; j++) bK[j] = 0xFFFFFFFFFFFFFFFFull;
    unsigned thr = 0xFFFFFFFFu;                    // NaN bits until 16 filled

    const float4* sp = g_spos4 + (size_t)b * Nk;
    const int*    si = g_sidx  + (size_t)b * Nk;
    const int*    cs = g_cellStart[b];
    const float h = 1.0f / (float)G;

#define SLABD(qc, c) fmaxf(0.f, fmaxf((float)(c) * h - (qc), (qc) - (float)((c) + 1) * h))

#define SEGMENT(J0, J1)                                                     \
    for (int base = (J0); base < (J1); base += 32) {                        \
        int j = base + lane;                                                \
        int act = j < (J1);                                                 \
        int jc = act ? j : (J1) - 1;                                        \
        float4 pt = sp[jc];                                                 \
        float qk = fmaf(qz, pt.z, fmaf(qy, pt.y, qx * pt.x));               \
        float d2 = (qq - 2.f * qk) + pt.w;                                  \
        unsigned d2b = __float_as_uint(d2);                                 \
        int pass = act && d2b <= thr;                                       \
        ull key = 0;                                                        \
        if (pass) key = ((ull)d2b << 32) | (ull)PERM(si[jc]);               \
        unsigned m = __ballot_sync(FULLM, pass);                            \
        while (m) {                                                         \
            int src = __ffs(m) - 1; m &= m - 1;                             \
            unsigned klo = __shfl_sync(FULLM, (unsigned)key, src);          \
            unsigned khi = __shfl_sync(FULLM, (unsigned)(key >> 32), src);  \
            ull ck = ((ull)khi << 32) | (ull)klo;                           \
            if (ck < bK[KK - 1]) {                                          \
                bK[KK - 1] = ck;                                            \
                _Pragma("unroll")                                           \
                for (int jj = KK - 1; jj > 0; jj--) {                       \
                    if (bK[jj] < bK[jj - 1]) {                              \
                        ull tk = bK[jj]; bK[jj] = bK[jj - 1]; bK[jj - 1] = tk; \
                    } else break;                                           \
                }                                                           \
                thr = (unsigned)(bK[KK - 1] >> 32);                         \
            }                                                               \
        }                                                                   \
    }

    for (int r = 0; r < G; r++) {
        float thrF = __uint_as_float(thr);        // NaN until 16 found
        if (r >= 1) {
            int rIn = r - 1;
            float mg = 1e30f;
            if (cx - rIn > 0)     mg = fminf(mg, qx - (float)(cx - rIn) * h);
            if (cx + rIn < G - 1) mg = fminf(mg, (float)(cx + rIn + 1) * h - qx);
            if (cy - rIn > 0)     mg = fminf(mg, qy - (float)(cy - rIn) * h);
            if (cy + rIn < G - 1) mg = fminf(mg, (float)(cy + rIn + 1) * h - qy);
            if (cz - rIn > 0)     mg = fminf(mg, qz - (float)(cz - rIn) * h);
            if (cz + rIn < G - 1) mg = fminf(mg, (float)(cz + rIn + 1) * h - qz);
            if (mg > 0.f && (mg * mg - 1e-5f) > thrF) break;   // warp-uniform
        }
        int zlo = max(0, cz - r), zhi = min(G - 1, cz + r);
        for (int iz = zlo; iz <= zhi; iz++) {
            int adz = iz - cz; if (adz < 0) adz = -adz;
            float dz = SLABD(qz, iz);
            float dz2 = dz * dz;
            if (dz2 - 1e-5f > thrF) continue;                  // plane prune (NaN-safe)
            int ylo = max(0, cy - r), yhi = min(G - 1, cy + r);
            for (int iy = ylo; iy <= yhi; iy++) {
                int ady = iy - cy; if (ady < 0) ady = -ady;
                float dy = SLABD(qy, iy);
                float rowMin = dz2 + dy * dy;
                if (rowMin - 1e-5f > thrF) continue;           // row prune (NaN-safe)
                int rowBase = (iz * G + iy) * G;
                if (adz == r || ady == r) {
                    int xlo = max(0, cx - r), xhi = min(G - 1, cx + r);
                    int j0 = cs[rowBase + xlo], j1 = cs[rowBase + xhi + 1];
                    SEGMENT(j0, j1)
                } else {
                    if (cx - r >= 0) {
                        float dx = SLABD(qx, cx - r);
                        if (!(rowMin + dx * dx - 1e-5f > thrF)) {
                            int c = rowBase + cx - r;
                            int j0 = cs[c], j1 = cs[c + 1];
                            SEGMENT(j0, j1)
                        }
                    }
                    if (cx + r <= G - 1) {
                        float dx = SLABD(qx, cx + r);
                        if (!(rowMin + dx * dx - 1e-5f > thrF)) {
                            int c = rowBase + cx + r;
                            int j0 = cs[c], j1 = cs[c + 1];
                            SEGMENT(j0, j1)
                        }
                    }
                }
            }
        }
    }
#undef SEGMENT
#undef SLABD

    // ---- fused PE + softmax: 2 lanes per neighbor ----
    int nbr = lane >> 1;
    int half = lane & 1;
    ull myKey = bK[0];
    #pragma unroll
    for (int r2 = 1; r2 < KK; r2++) if (nbr == r2) myKey = bK[r2];
    unsigned pm = (unsigned)(myKey & 0x3FFFull);
    int myn = (int)(((pm & 31u) << 9) | (pm >> 5));

    const float* kp = k_pos + ((size_t)b * Nk + myn) * 3;
    float rx = qx - kp[0], ry = qy - kp[1], rz = qz - kp[2];
    float acc = 0.f;
    int i0 = half * 64;
    #pragma unroll 8
    for (int i = i0; i < i0 + 64; i++) {
        float hh = fmaf(sW1[i * 3], rx, fmaf(sW1[i * 3 + 1], ry, fmaf(sW1[i * 3 + 2], rz, sb1[i])));
        hh = fmaxf(hh, 0.f);
        acc = fmaf(sc2[i], hh, acc);
    }
    acc += __shfl_xor_sync(FULLM, acc, 1);
    float score = g_qsum[gq] - g_ksum[b * Nk + myn] + acc + g_consts[2];

    float mx = score;
    #pragma unroll
    for (int o = 2; o <= 16; o <<= 1) mx = fmaxf(mx, __shfl_xor_sync(FULLM, mx, o));
    float e = expf(score - mx);
    float sum = e;
    #pragma unroll
    for (int o = 2; o <= 16; o <<= 1) sum += __shfl_xor_sync(FULLM, sum, o);
    if (half == 0) {
        int gi = gq * KK + nbr;
        g_attn[gi] = e / sum;
        g_nidx[gi] = myn;
    }
}

// ---------------- column sums of attn over S, per (b, slot j) ----------------
__global__ __launch_bounds__(256) void colsum_kernel() {
    int b = blockIdx.x >> 4, j = blockIdx.x & 15;
    float s = 0.f;
    for (int ss = threadIdx.x; ss < Sq; ss += 256) s += g_attn[(b * Sq + ss) * KK + j];
    #pragma unroll
    for (int o = 16; o; o >>= 1) s += __shfl_xor_sync(FULLM, s, o);
    __shared__ float r[8];
    if ((threadIdx.x & 31) == 0) r[threadIdx.x >> 5] = s;
    __syncthreads();
    if (threadIdx.x == 0) {
        float tt = 0.f;
        #pragma unroll
        for (int w = 0; w < 8; w++) tt += r[w];
        g_acol[blockIdx.x] = tt;
    }
}

// ---------------- final: normalized gather-aggregate + single GEMM row ----------------
__global__ __launch_bounds__(128) void final_kernel(const float* __restrict__ k_feat,
                                                    const float* __restrict__ Wv,
                                                    const float* __restrict__ bv,
                                                    float* __restrict__ out) {
    constexpr int QPB2 = 8;
    extern __shared__ float sm[];
    float* WvS  = sm;                    // 128 rows x 132 stride (padded, conflict-free f4)
    float* sAgg = sm + 128 * 132;        // 128
    float* sA   = sAgg + 128;            // 16
    int*   sI   = (int*)(sA + 16);       // 16

    int t = threadIdx.x;
    for (int id = t; id < 128 * 32; id += 128) {
        int o = id >> 5, i4 = id & 31;
        float4 w = ((const float4*)Wv)[id];
        ((float4*)(WvS + o * 132))[i4] = w;
    }
    float bvt = bv[t];

    for (int ql = 0; ql < QPB2; ql++) {
        int gq = blockIdx.x * QPB2 + ql;
        int b = gq >> 10;
        __syncthreads();
        if (t < 16) {
            float a = g_attn[gq * KK + t];
            a = a / (g_acol[b * KK + t] + 1e-6f);
            sA[t] = a;
            sI[t] = g_nidx[gq * KK + t];
        }
        __syncthreads();

        float agg = 0.f, asum = 0.f;
        #pragma unroll
        for (int j = 0; j < KK; j++) {
            float a = sA[j];
            asum += a;
            const float* vr = k_feat + ((size_t)(b * Nk) + sI[j]) * 128;
            agg = fmaf(a, vr[t], agg);
        }
        sAgg[t] = agg;
        __syncthreads();

        float a0 = 0.f, a1 = 0.f, a2 = 0.f, a3 = 0.f;
        const float4* wrow = (const float4*)(WvS + t * 132);
        const float4* aggv = (const float4*)sAgg;
        #pragma unroll
        for (int i4 = 0; i4 < 32; i4++) {
            float4 w = wrow[i4];
            float4 g = aggv[i4];
            a0 = fmaf(w.x, g.x, a0);
            a1 = fmaf(w.y, g.y, a1);
            a2 = fmaf(w.z, g.z, a2);
            a3 = fmaf(w.w, g.w, a3);
        }
        out[(size_t)gq * 128 + t] = ((a0 + a1) + (a2 + a3)) + asum * bvt;
    }
}

// ---------------- launch ----------------
extern "C" void kernel_launch(void* const* d_in, const int* in_sizes, int n_in,
                              void* d_out, int out_size) {
    const float* q_feat = (const float*)d_in[0];
    const float* k_feat = (const float*)d_in[1];
    const float* q_pos  = (const float*)d_in[2];
    const float* k_pos  = (const float*)d_in[3];
    const float* Wq     = (const float*)d_in[4];
    const float* bq     = (const float*)d_in[5];
    const float* Wk     = (const float*)d_in[6];
    const float* bk     = (const float*)d_in[7];
    const float* Wv     = (const float*)d_in[8];
    const float* bv     = (const float*)d_in[9];
    const float* W1     = (const float*)d_in[10];
    const float* b1     = (const float*)d_in[11];
    const float* W2     = (const float*)d_in[12];
    const float* b2     = (const float*)d_in[13];
    float* out = (float*)d_out;

    prep_zero_kernel<<<129, 384>>>(Wq, bq, Wk, bk, W2, b2);
    count_rowsum_kernel<<<RS_CTAS + CNT_CTAS, 256>>>(k_pos, q_pos, k_feat, q_feat);
    scan_kernel<<<2 * Bq, 1024>>>();
    scatter_all_kernel<<<(Bq * (Nk + Sq)) / 256, 256>>>(k_pos, q_pos);
    knn_warp_kernel<<<(Bq * Sq * 32) / 256, 256>>>(q_pos, k_pos, W1, b1);
    colsum_kernel<<<Bq * KK, 256>>>();

    int smemF = (128 * 132 + 128 + 16 + 16) * (int)sizeof(float);
    cudaFuncSetAttribute(final_kernel, cudaFuncAttributeMaxDynamicSharedMemorySize, smemF);
    final_kernel<<<(Bq * Sq) / 8, 128, smemF>>>(k_feat, Wv, bv, out);
}